// round 14
// baseline (speedup 1.0000x reference)
#include <cuda_runtime.h>
#include <cuda_fp16.h>
#include <math.h>
#include <stdint.h>

// Problem constants
#define NUM_K  1024
#define DIM    256
#define HWSZ   1024
#define NTOK   32768
#define DECAYF 0.99f
#define OMD    0.01f
#define CCOST  0.25f
#define EPSF   1e-5f
#define EPS_AMBIG 0.08f

// Output layout
#define OFF_Q    0
#define OFF_LOSS 8388608
#define OFF_PERP 8388609
#define OFF_CB   8388610
#define OFF_CS   8650754
#define OFF_EDW  8651778

// Scratch
__device__ float g_cnorm[NUM_K];
__device__ int   g_counts[NUM_K];
__device__ int   g_idx[NTOK];
__device__ float g_zpart[1024];
__device__ float g_minpart[256];
__device__ float g_csadj[NUM_K];
__device__ int   g_off[NUM_K];
__device__ int   g_cur[NUM_K];
__device__ int   g_toklist[NTOK];
__device__ int   g_flagcnt;
__device__ int   g_flaglist[NTOK];

// fp16 splits (token-major / code-major, 256 cols, K contiguous)
__device__ __align__(16) __half g_zh[NTOK * DIM];
__device__ __align__(16) __half g_zl[NTOK * DIM];
__device__ __align__(16) __half g_ch[NUM_K * DIM];

__device__ __forceinline__ void split2(float x, __half& h, __half& l) {
    h = __float2half_rn(x);
    l = __float2half_rn(x - __half2float(h));
}
__device__ __forceinline__ uint32_t smem_u32(const void* p) {
    uint32_t a;
    asm("{ .reg .u64 t; cvta.to.shared.u64 t, %1; cvt.u32.u64 %0, t; }" : "=r"(a) : "l"(p));
    return a;
}
__device__ __forceinline__ void ldm_x4(uint32_t& r0, uint32_t& r1, uint32_t& r2, uint32_t& r3, uint32_t addr) {
    asm volatile("ldmatrix.sync.aligned.m8n8.x4.shared.b16 {%0,%1,%2,%3}, [%4];"
                 : "=r"(r0), "=r"(r1), "=r"(r2), "=r"(r3) : "r"(addr));
}
__device__ __forceinline__ void mma_f16(float* c, const uint32_t* a, uint32_t b0, uint32_t b1) {
    asm volatile("mma.sync.aligned.m16n8k16.row.col.f32.f16.f16.f32 "
                 "{%0,%1,%2,%3}, {%4,%5,%6,%7}, {%8,%9}, {%0,%1,%2,%3};"
                 : "+f"(c[0]), "+f"(c[1]), "+f"(c[2]), "+f"(c[3])
                 : "r"(a[0]), "r"(a[1]), "r"(a[2]), "r"(a[3]), "r"(b0), "r"(b1));
}
__device__ __forceinline__ void cp16(uint32_t dst, const void* src) {
    asm volatile("cp.async.cg.shared.global [%0], [%1], 16;" :: "r"(dst), "l"(src));
}
__device__ __forceinline__ void cp_commit() { asm volatile("cp.async.commit_group;" ::: "memory"); }
template<int N> __device__ __forceinline__ void cp_wait() {
    asm volatile("cp.async.wait_group %0;" :: "n"(N) : "memory");
}

// ---------------------------------------------------------------------------
// K1: codebook norms + fp16 hi split + clears. grid=1024, block=64
// ---------------------------------------------------------------------------
__global__ void k_init(const float* __restrict__ cb) {
    const int k = blockIdx.x;
    const int t = threadIdx.x;
    const float4 c4 = ((const float4*)(cb + k * DIM))[t];
    float s = c4.x * c4.x + c4.y * c4.y + c4.z * c4.z + c4.w * c4.w;
    #pragma unroll
    for (int o = 16; o > 0; o >>= 1) s += __shfl_xor_sync(0xffffffffu, s, o);
    __shared__ float red[2];
    if ((t & 31) == 0) red[t >> 5] = s;
    #pragma unroll
    for (int j = 0; j < 4; j++) {
        const int d = t + 64 * j;
        g_ch[k * DIM + d] = __float2half_rn(cb[k * DIM + d]);
    }
    __syncthreads();
    if (t == 0) {
        g_cnorm[k]  = red[0] + red[1];
        g_counts[k] = 0;
        if (k == 0) g_flagcnt = 0;
    }
}

// ---------------------------------------------------------------------------
// K2: transpose + fp16-split z + ||z||^2 partial. grid=1024, block=256
// ---------------------------------------------------------------------------
__global__ __launch_bounds__(256)
void k_zsplit(const float* __restrict__ z) {
    __shared__ float s[256][33];
    __shared__ float zred[8];
    const int b    = blockIdx.x >> 5;
    const int hwc  = blockIdx.x & 31;
    const int tid  = threadIdx.x;
    const int lane = tid & 31;
    const int grp  = tid >> 5;

    const float* zb = z + (size_t)b * DIM * HWSZ + hwc * 32;
    #pragma unroll 8
    for (int dd = 0; dd < 32; ++dd) {
        const int d = grp * 32 + dd;
        s[d][lane] = zb[(size_t)d * HWSZ + lane];
    }
    __syncthreads();

    float zacc = 0.f;
    #pragma unroll
    for (int tg = 0; tg < 4; ++tg) {
        const int tok = tg * 8 + grp;
        const size_t rowo = ((size_t)(b * HWSZ + hwc * 32 + tok)) * DIM;
        #pragma unroll
        for (int j = 0; j < 4; ++j) {
            const int d0 = (j * 32 + lane) * 2;
            const float x0 = s[d0][tok];
            const float x1 = s[d0 + 1][tok];
            zacc = fmaf(x0, x0, zacc);
            zacc = fmaf(x1, x1, zacc);
            __half h0, l0, h1, l1;
            split2(x0, h0, l0);
            split2(x1, h1, l1);
            *(__half2*)(g_zh + rowo + d0) = __halves2half2(h0, h1);
            *(__half2*)(g_zl + rowo + d0) = __halves2half2(l0, l1);
        }
    }
    #pragma unroll
    for (int o = 16; o > 0; o >>= 1) zacc += __shfl_xor_sync(0xffffffffu, zacc, o);
    if (lane == 0) zred[grp] = zacc;
    __syncthreads();
    if (tid == 0) {
        float t = 0.f;
        #pragma unroll
        for (int i = 0; i < 8; ++i) t += zred[i];
        g_zpart[blockIdx.x] = t;
    }
}

// ---------------------------------------------------------------------------
// K3: 1-term fp16 coarse GEMM + top2-argmin + flag + loss + fused Q-gather.
// grid=256 CTAs (128 tokens), block=512 (16 warps: 4M x 4N), warp 32x64.
// ---------------------------------------------------------------------------
#define RSTR    80
#define A_VST   (128 * RSTR)             // 10240
#define B_BASE  A_VST                    // 10240
#define STAGE_B (A_VST + 256 * RSTR)     // 30720
#define SMIN_O  (3 * STAGE_B)            // 92160
#define SMINI_O (SMIN_O + 2048)          // 94208
#define SMIN2_O (SMINI_O + 2048)         // 96256
#define CNS_O   (SMIN2_O + 2048)         // 98304
#define SMEM_TOTAL (CNS_O + 4096)        // 102400

__global__ __launch_bounds__(512, 1)
void k_argmin_mma(const float* __restrict__ cb, float* __restrict__ out) {
    extern __shared__ char smem[];
    const uint32_t sb = smem_u32(smem);

    const int tid   = threadIdx.x;
    const int lane  = tid & 31;
    const int wid   = tid >> 5;
    const int warpM = wid & 3;
    const int warpN = wid >> 2;
    const int gid   = lane >> 2;
    const int tq    = lane & 3;
    const int tok0  = blockIdx.x * 128;

    float acc[2][8][4];
    #pragma unroll
    for (int mt = 0; mt < 2; ++mt)
        #pragma unroll
        for (int nt = 0; nt < 8; ++nt)
            #pragma unroll
            for (int c = 0; c < 4; ++c) acc[mt][nt][c] = 0.f;

    // top-2 tracking per slot [mt][h]
    float v1[2][2], v2[2][2];
    int   i1[2][2];
    #pragma unroll
    for (int mt = 0; mt < 2; ++mt)
        #pragma unroll
        for (int h = 0; h < 2; ++h) { v1[mt][h] = 3.4e38f; v2[mt][h] = 3.4e38f; i1[mt][h] = 0; }

    const int a_row  = (lane & 15);
    const int a_coff = ((lane >> 4) & 1) * 16;
    const int b_row  = ((lane & 16) >> 1) + (lane & 7);
    const int b_coff = ((lane >> 3) & 1) * 16;

    float* cns = (float*)(smem + CNS_O);
    cns[tid] = g_cnorm[tid];
    cns[tid + 512] = g_cnorm[tid + 512];

    auto stage_issue = [&](int cc, uint32_t sbase) {
        const int ct = cc >> 3;
        const int kc = cc & 7;
        {   // A: 512 slots, 1 per thread
            const int row = tid >> 2;
            const int q = tid & 3;
            cp16(sbase + row * RSTR + q * 16,
                 g_zh + (((size_t)(tok0 + row)) << 8) + kc * 32 + q * 8);
        }
        #pragma unroll
        for (int jj = 0; jj < 2; ++jj) {   // B: 1024 slots, 2 per thread
            const int i = tid + jj * 512;
            const int row = i >> 2;
            const int q = i & 3;
            cp16(sbase + B_BASE + row * RSTR + q * 16,
                 g_ch + (((size_t)(ct * 256 + row)) << 8) + kc * 32 + q * 8);
        }
        cp_commit();
    };

    stage_issue(0, sb);
    stage_issue(1, sb + STAGE_B);

    int sidx = 0;
    for (int cc = 0; cc < 32; ++cc) {
        if (cc < 31) cp_wait<1>(); else cp_wait<0>();
        __syncthreads();
        if (cc + 2 < 32) {
            int nidx = sidx + 2; if (nidx >= 3) nidx -= 3;
            stage_issue(cc + 2, sb + nidx * STAGE_B);
        }

        const uint32_t abase = sb + sidx * STAGE_B;
        const uint32_t bbase = abase + B_BASE;

        #pragma unroll
        for (int kg = 0; kg < 2; ++kg) {
            uint32_t ah[2][4];
            #pragma unroll
            for (int mt = 0; mt < 2; ++mt) {
                const uint32_t ar = (warpM * 32 + mt * 16 + a_row) * RSTR + kg * 32 + a_coff;
                ldm_x4(ah[mt][0], ah[mt][1], ah[mt][2], ah[mt][3], abase + ar);
            }
            #pragma unroll
            for (int p = 0; p < 4; ++p) {
                const uint32_t br = (warpN * 64 + p * 16 + b_row) * RSTR + kg * 32 + b_coff;
                uint32_t b0, b1, b2, b3;
                ldm_x4(b0, b1, b2, b3, bbase + br);
                #pragma unroll
                for (int mt = 0; mt < 2; ++mt) {
                    mma_f16(acc[mt][2 * p],     ah[mt], b0, b1);
                    mma_f16(acc[mt][2 * p + 1], ah[mt], b2, b3);
                }
            }
        }

        if ((cc & 7) == 7) {
            const int ct = cc >> 3;
            #pragma unroll
            for (int mt = 0; mt < 2; ++mt) {
                #pragma unroll
                for (int nt = 0; nt < 8; ++nt) {
                    const int n0 = ct * 256 + warpN * 64 + nt * 8 + 2 * tq;
                    const float cn0 = cns[n0];
                    const float cn1 = cns[n0 + 1];
                    const float sc[2][2] = {
                        { fmaf(-2.f, acc[mt][nt][0], cn0), fmaf(-2.f, acc[mt][nt][1], cn1) },
                        { fmaf(-2.f, acc[mt][nt][2], cn0), fmaf(-2.f, acc[mt][nt][3], cn1) } };
                    #pragma unroll
                    for (int h = 0; h < 2; ++h) {
                        #pragma unroll
                        for (int c = 0; c < 2; ++c) {
                            const float s = sc[h][c];
                            if (s < v1[mt][h]) { v2[mt][h] = v1[mt][h]; v1[mt][h] = s; i1[mt][h] = n0 + c; }
                            else if (s < v2[mt][h]) v2[mt][h] = s;
                        }
                    }
                    acc[mt][nt][0] = acc[mt][nt][1] = acc[mt][nt][2] = acc[mt][nt][3] = 0.f;
                }
            }
        }
        if (++sidx >= 3) sidx -= 3;
    }

    // cross-tq reduce of (v1, i1, v2)
    float* sminv  = (float*)(smem + SMIN_O);
    int*   smini  = (int*)(smem + SMINI_O);
    float* sminv2 = (float*)(smem + SMIN2_O);
    #pragma unroll
    for (int mt = 0; mt < 2; ++mt) {
        #pragma unroll
        for (int h = 0; h < 2; ++h) {
            float a1 = v1[mt][h], a2 = v2[mt][h];
            int   ai = i1[mt][h];
            #pragma unroll
            for (int off = 1; off <= 2; off <<= 1) {
                const float b1 = __shfl_xor_sync(0xffffffffu, a1, off);
                const int   bi = __shfl_xor_sync(0xffffffffu, ai, off);
                const float b2 = __shfl_xor_sync(0xffffffffu, a2, off);
                float loser;
                if (b1 < a1 || (b1 == a1 && bi < ai)) { loser = a1; a1 = b1; ai = bi; }
                else loser = b1;
                a2 = fminf(loser, fminf(a2, b2));
            }
            if (tq == 0) {
                const int row = warpM * 32 + mt * 16 + h * 8 + gid;
                sminv [warpN * 128 + row] = a1;
                smini [warpN * 128 + row] = ai;
                sminv2[warpN * 128 + row] = a2;
            }
        }
    }
    __syncthreads();

    // combine 4 warpN partials; write idx/counts/flags; stage loss partials
    if (tid < 128) {
        float a1 = sminv[tid], a2 = sminv2[tid];
        int   ai = smini[tid];
        #pragma unroll
        for (int wn = 1; wn < 4; ++wn) {
            const float b1 = sminv[wn * 128 + tid];
            const int   bi = smini[wn * 128 + tid];
            const float b2 = sminv2[wn * 128 + tid];
            float loser;
            if (b1 < a1 || (b1 == a1 && bi < ai)) { loser = a1; a1 = b1; ai = bi; }
            else loser = b1;
            a2 = fminf(loser, fminf(a2, b2));
        }
        const int tok = tok0 + tid;
        g_idx[tok] = ai;
        atomicAdd(&g_counts[ai], 1);
        if (a2 - a1 < EPS_AMBIG) {
            const int pos = atomicAdd(&g_flagcnt, 1);
            g_flaglist[pos] = tok;
        }
        float sum = a1;
        #pragma unroll
        for (int o = 16; o > 0; o >>= 1) sum += __shfl_xor_sync(0xffffffffu, sum, o);
        if (lane == 0) cns[wid] = sum;
        smini[tid] = ai;
    }
    __syncthreads();
    if (tid == 0)
        g_minpart[blockIdx.x] = (cns[0] + cns[1]) + (cns[2] + cns[3]);

    // fused quantized-output gather (coarse idx; recheck fixes rare flips)
    {
        float* cshare = (float*)smem;
        const int b   = tok0 >> 10;
        const int hw0 = tok0 & 1023;
        const int w   = tid >> 5;
        #pragma unroll
        for (int g = 0; g < 4; ++g) {
            #pragma unroll
            for (int j = 0; j < 4; ++j) {
                const int slot = tid + j * 512;
                const int row  = slot >> 6;
                const int q    = slot & 63;
                const float4 v = __ldg((const float4*)(cb + (size_t)smini[g * 32 + row] * DIM) + q);
                float* cd = cshare + row * 257 + q * 4;
                cd[0] = v.x; cd[1] = v.y; cd[2] = v.z; cd[3] = v.w;
            }
            __syncthreads();
            float* qbase = out + OFF_Q + (size_t)b * DIM * HWSZ + hw0 + g * 32 + lane;
            #pragma unroll
            for (int dd = 0; dd < 16; ++dd) {
                const int d = w + dd * 16;
                qbase[(size_t)d * HWSZ] = cshare[lane * 257 + d];
            }
            __syncthreads();
        }
    }
}

// ---------------------------------------------------------------------------
// K4: exact fp32 recheck of flagged tokens (full codebook scan).
// grid=128 CTAs, 256 threads; 4 tokens per CTA iteration.
// ---------------------------------------------------------------------------
__global__ __launch_bounds__(256)
void k_recheck(const float* __restrict__ cb, float* __restrict__ out) {
    __shared__ float zr[4][256];
    __shared__ int   stoks[4];
    __shared__ float mv[8][4];
    __shared__ int   mi[8][4];
    __shared__ int   sflip[4];

    const int tid  = threadIdx.x;
    const int lane = tid & 31;
    const int w    = tid >> 5;
    const int cnt  = g_flagcnt;

    for (int base = blockIdx.x * 4; base < cnt; base += gridDim.x * 4) {
        const int nt = min(4, cnt - base);
        if (tid < nt) stoks[tid] = g_flaglist[base + tid];
        __syncthreads();
        for (int t = 0; t < nt; ++t) {
            const size_t o = ((size_t)stoks[t] << 8) + tid;
            zr[t][tid] = __half2float(g_zh[o]) + __half2float(g_zl[o]);
        }
        __syncthreads();

        float bv[4] = {3.4e38f, 3.4e38f, 3.4e38f, 3.4e38f};
        int   bi[4] = {0, 0, 0, 0};
        for (int j = 0; j < 128; ++j) {
            const int code = w * 128 + j;
            const float* crow = cb + (size_t)code * DIM;
            float c8[8];
            #pragma unroll
            for (int k2 = 0; k2 < 8; ++k2) c8[k2] = __ldg(crow + lane + 32 * k2);
            const float cn = __ldg(&g_cnorm[code]);
            #pragma unroll
            for (int t = 0; t < 4; ++t) {
                if (t >= nt) break;
                float p = 0.f;
                #pragma unroll
                for (int k2 = 0; k2 < 8; ++k2) p = fmaf(c8[k2], zr[t][lane + 32 * k2], p);
                #pragma unroll
                for (int o = 16; o > 0; o >>= 1) p += __shfl_xor_sync(0xffffffffu, p, o);
                const float s = cn - 2.f * p;
                if (s < bv[t]) { bv[t] = s; bi[t] = code; }   // ascending codes: strict <
            }
        }
        if (lane == 0) {
            #pragma unroll
            for (int t = 0; t < 4; ++t) { mv[w][t] = bv[t]; mi[w][t] = bi[t]; }
        }
        __syncthreads();

        if (tid < nt) {
            float v = mv[0][tid];
            int   i = mi[0][tid];
            #pragma unroll
            for (int ww = 1; ww < 8; ++ww) {
                const float ov = mv[ww][tid];
                const int   oi = mi[ww][tid];
                if (ov < v || (ov == v && oi < i)) { v = ov; i = oi; }
            }
            const int tok = stoks[tid];
            const int old = g_idx[tok];
            if (i != old) {
                atomicSub(&g_counts[old], 1);
                atomicAdd(&g_counts[i], 1);
                g_idx[tok] = i;
                sflip[tid] = i;
            } else sflip[tid] = -1;
        }
        __syncthreads();

        for (int t = 0; t < nt; ++t) {
            const int ni = sflip[t];
            if (ni >= 0) {   // rewrite quantized-output row for flipped token
                const int tok = stoks[t];
                const int b = tok >> 10, hw = tok & 1023;
                out[OFF_Q + (size_t)b * DIM * HWSZ + (size_t)tid * HWSZ + hw] =
                    __ldg(cb + (size_t)ni * DIM + tid);
            }
        }
        __syncthreads();
    }
}

// ---------------------------------------------------------------------------
// K5: offsets scan + EMA + perplexity + loss. 1 block, 1024 threads
// ---------------------------------------------------------------------------
__global__ void k_offfin(const float* __restrict__ ema_cs, float* __restrict__ out) {
    __shared__ int   sc[NUM_K];
    __shared__ float red[32];
    __shared__ float nsh, zsh;
    const int t = threadIdx.x;
    const int c = g_counts[t];

    sc[t] = c;
    __syncthreads();
    for (int off = 1; off < NUM_K; off <<= 1) {
        const int v = (t >= off) ? sc[t - off] : 0;
        __syncthreads();
        sc[t] += v;
        __syncthreads();
    }
    const int excl = sc[t] - c;
    g_off[t] = excl;
    g_cur[t] = excl;

    float zs = g_zpart[t] + ((t < 256) ? g_minpart[t] : 0.f);
    #pragma unroll
    for (int o = 16; o > 0; o >>= 1) zs += __shfl_xor_sync(0xffffffffu, zs, o);
    if ((t & 31) == 0) red[t >> 5] = zs;
    __syncthreads();
    if (t < 32) {
        float x = red[t];
        #pragma unroll
        for (int o = 16; o > 0; o >>= 1) x += __shfl_xor_sync(0xffffffffu, x, o);
        if (t == 0) zsh = x;
    }
    __syncthreads();

    const float cnt = (float)c;
    const float ncs = ema_cs[t] * DECAYF + OMD * cnt;
    out[OFF_CS + t] = ncs;

    float s = ncs;
    #pragma unroll
    for (int o = 16; o > 0; o >>= 1) s += __shfl_xor_sync(0xffffffffu, s, o);
    if ((t & 31) == 0) red[t >> 5] = s;
    __syncthreads();
    if (t < 32) {
        float x = red[t];
        #pragma unroll
        for (int o = 16; o > 0; o >>= 1) x += __shfl_xor_sync(0xffffffffu, x, o);
        if (t == 0) nsh = x;
    }
    __syncthreads();
    const float n = nsh;
    g_csadj[t] = (ncs + EPSF) / (n + NUM_K * EPSF) * n;

    const float p = cnt / (float)NTOK;
    float s2 = p * logf(p + 1e-10f);
    #pragma unroll
    for (int o = 16; o > 0; o >>= 1) s2 += __shfl_xor_sync(0xffffffffu, s2, o);
    if ((t & 31) == 0) red[t >> 5] = s2;
    __syncthreads();
    if (t == 0) {
        float x = 0.f;
        #pragma unroll
        for (int i = 0; i < 32; i++) x += red[i];
        out[OFF_PERP] = expf(-x);
        out[OFF_LOSS] = CCOST * zsh / (float)(NTOK * DIM);
    }
}

// ---------------------------------------------------------------------------
// K6: bucket tokens by code. grid=128, block=256
// ---------------------------------------------------------------------------
__global__ void k_bucket() {
    const int tok = blockIdx.x * 256 + threadIdx.x;
    const int k = g_idx[tok];
    const int pos = atomicAdd(&g_cur[k], 1);
    g_toklist[pos] = tok;
}

// ---------------------------------------------------------------------------
// K7: dw gather (smem token list) + EMA + codebook division. grid=1024, block=256
// ---------------------------------------------------------------------------
#define MAXB 128
__global__ __launch_bounds__(256)
void k_dwfin(const float* __restrict__ ema_dw, float* __restrict__ out) {
    __shared__ int stok[MAXB];
    const int k = blockIdx.x;
    const int d = threadIdx.x;
    const int start = g_off[k];
    const int cnt   = g_counts[k];

    for (int i = d; i < cnt && i < MAXB; i += 256) stok[i] = g_toklist[start + i];
    __syncthreads();

    float acc = 0.f;
    const int csmem = (cnt < MAXB) ? cnt : MAXB;
    int i = 0;
    for (; i + 4 <= csmem; i += 4) {
        const int t0 = stok[i], t1 = stok[i + 1], t2 = stok[i + 2], t3 = stok[i + 3];
        const float v0 = __half2float(g_zh[((size_t)t0 << 8) + d]) + __half2float(g_zl[((size_t)t0 << 8) + d]);
        const float v1 = __half2float(g_zh[((size_t)t1 << 8) + d]) + __half2float(g_zl[((size_t)t1 << 8) + d]);
        const float v2 = __half2float(g_zh[((size_t)t2 << 8) + d]) + __half2float(g_zl[((size_t)t2 << 8) + d]);
        const float v3 = __half2float(g_zh[((size_t)t3 << 8) + d]) + __half2float(g_zl[((size_t)t3 << 8) + d]);
        acc += (v0 + v1) + (v2 + v3);
    }
    for (; i < csmem; ++i) {
        const size_t o = ((size_t)stok[i] << 8) + d;
        acc += __half2float(g_zh[o]) + __half2float(g_zl[o]);
    }
    for (int j = MAXB; j < cnt; ++j) {
        const size_t o = ((size_t)g_toklist[start + j] << 8) + d;
        acc += __half2float(g_zh[o]) + __half2float(g_zl[o]);
    }

    const size_t o = (size_t)k * DIM + d;
    const float nd = ema_dw[o] * DECAYF + OMD * acc;
    out[OFF_EDW + o] = nd;
    out[OFF_CB  + o] = nd / g_csadj[k];
}

// ---------------------------------------------------------------------------
extern "C" void kernel_launch(void* const* d_in, const int* in_sizes, int n_in,
                              void* d_out, int out_size) {
    const float* z      = (const float*)d_in[0];
    const float* cb     = (const float*)d_in[1];
    const float* ema_cs = (const float*)d_in[2];
    const float* ema_dw = (const float*)d_in[3];
    float* out = (float*)d_out;

    cudaFuncSetAttribute(k_argmin_mma, cudaFuncAttributeMaxDynamicSharedMemorySize, SMEM_TOTAL);

    k_init<<<NUM_K, 64>>>(cb);
    k_zsplit<<<1024, 256>>>(z);
    k_argmin_mma<<<NTOK / 128, 512, SMEM_TOTAL>>>(cb, out);
    k_recheck<<<128, 256>>>(cb, out);
    k_offfin<<<1, 1024>>>(ema_cs, out);
    k_bucket<<<NTOK / 256, 256>>>();
    k_dwfin<<<NUM_K, 256>>>(ema_dw, out);
}

// round 15
// speedup vs baseline: 1.0414x; 1.0414x over previous
#include <cuda_runtime.h>
#include <cuda_fp16.h>
#include <math.h>
#include <stdint.h>

// Problem constants
#define NUM_K  1024
#define DIM    256
#define HWSZ   1024
#define NTOK   32768
#define DECAYF 0.99f
#define OMD    0.01f
#define CCOST  0.25f
#define EPSF   1e-5f
#define EPS_AMBIG 0.08f

// Output layout
#define OFF_Q    0
#define OFF_LOSS 8388608
#define OFF_PERP 8388609
#define OFF_CB   8388610
#define OFF_CS   8650754
#define OFF_EDW  8651778

// Scratch
__device__ float g_cnorm[NUM_K];
__device__ int   g_counts[NUM_K];
__device__ int   g_idx[NTOK];
__device__ float g_zpart[1024];
__device__ float g_minpart[256];
__device__ float g_csadj[NUM_K];
__device__ int   g_off[NUM_K];
__device__ int   g_cur[NUM_K];
__device__ int   g_toklist[NTOK];
__device__ int   g_flagcnt;
__device__ int   g_flaglist[NTOK];

// fp16 splits (token-major / code-major, 256 cols, K contiguous)
__device__ __align__(16) __half g_zh[NTOK * DIM];
__device__ __align__(16) __half g_zl[NTOK * DIM];
__device__ __align__(16) __half g_ch[NUM_K * DIM];
__device__ __align__(16) __half g_cl[NUM_K * DIM];

__device__ __forceinline__ void split2(float x, __half& h, __half& l) {
    h = __float2half_rn(x);
    l = __float2half_rn(x - __half2float(h));
}
__device__ __forceinline__ uint32_t smem_u32(const void* p) {
    uint32_t a;
    asm("{ .reg .u64 t; cvta.to.shared.u64 t, %1; cvt.u32.u64 %0, t; }" : "=r"(a) : "l"(p));
    return a;
}
__device__ __forceinline__ void ldm_x4(uint32_t& r0, uint32_t& r1, uint32_t& r2, uint32_t& r3, uint32_t addr) {
    asm volatile("ldmatrix.sync.aligned.m8n8.x4.shared.b16 {%0,%1,%2,%3}, [%4];"
                 : "=r"(r0), "=r"(r1), "=r"(r2), "=r"(r3) : "r"(addr));
}
__device__ __forceinline__ void mma_f16(float* c, const uint32_t* a, uint32_t b0, uint32_t b1) {
    asm volatile("mma.sync.aligned.m16n8k16.row.col.f32.f16.f16.f32 "
                 "{%0,%1,%2,%3}, {%4,%5,%6,%7}, {%8,%9}, {%0,%1,%2,%3};"
                 : "+f"(c[0]), "+f"(c[1]), "+f"(c[2]), "+f"(c[3])
                 : "r"(a[0]), "r"(a[1]), "r"(a[2]), "r"(a[3]), "r"(b0), "r"(b1));
}
__device__ __forceinline__ void cp16(uint32_t dst, const void* src) {
    asm volatile("cp.async.cg.shared.global [%0], [%1], 16;" :: "r"(dst), "l"(src));
}
__device__ __forceinline__ void cp_commit() { asm volatile("cp.async.commit_group;" ::: "memory"); }
template<int N> __device__ __forceinline__ void cp_wait() {
    asm volatile("cp.async.wait_group %0;" :: "n"(N) : "memory");
}

// ---------------------------------------------------------------------------
// K1: codebook norms + fp16 splits (hi+lo) + clears. grid=1024, block=64
// ---------------------------------------------------------------------------
__global__ void k_init(const float* __restrict__ cb) {
    const int k = blockIdx.x;
    const int t = threadIdx.x;
    const float4 c4 = ((const float4*)(cb + k * DIM))[t];
    float s = c4.x * c4.x + c4.y * c4.y + c4.z * c4.z + c4.w * c4.w;
    #pragma unroll
    for (int o = 16; o > 0; o >>= 1) s += __shfl_xor_sync(0xffffffffu, s, o);
    __shared__ float red[2];
    if ((t & 31) == 0) red[t >> 5] = s;
    #pragma unroll
    for (int j = 0; j < 4; j++) {
        const int d = t + 64 * j;
        __half h, l;
        split2(cb[k * DIM + d], h, l);
        g_ch[k * DIM + d] = h;
        g_cl[k * DIM + d] = l;
    }
    __syncthreads();
    if (t == 0) {
        g_cnorm[k]  = red[0] + red[1];
        g_counts[k] = 0;
        if (k == 0) g_flagcnt = 0;
    }
}

// ---------------------------------------------------------------------------
// K2: transpose + fp16-split z + ||z||^2 partial. grid=1024, block=256
// ---------------------------------------------------------------------------
__global__ __launch_bounds__(256)
void k_zsplit(const float* __restrict__ z) {
    __shared__ float s[256][33];
    __shared__ float zred[8];
    const int b    = blockIdx.x >> 5;
    const int hwc  = blockIdx.x & 31;
    const int tid  = threadIdx.x;
    const int lane = tid & 31;
    const int grp  = tid >> 5;

    const float* zb = z + (size_t)b * DIM * HWSZ + hwc * 32;
    #pragma unroll 8
    for (int dd = 0; dd < 32; ++dd) {
        const int d = grp * 32 + dd;
        s[d][lane] = zb[(size_t)d * HWSZ + lane];
    }
    __syncthreads();

    float zacc = 0.f;
    #pragma unroll
    for (int tg = 0; tg < 4; ++tg) {
        const int tok = tg * 8 + grp;
        const size_t rowo = ((size_t)(b * HWSZ + hwc * 32 + tok)) * DIM;
        #pragma unroll
        for (int j = 0; j < 4; ++j) {
            const int d0 = (j * 32 + lane) * 2;
            const float x0 = s[d0][tok];
            const float x1 = s[d0 + 1][tok];
            zacc = fmaf(x0, x0, zacc);
            zacc = fmaf(x1, x1, zacc);
            __half h0, l0, h1, l1;
            split2(x0, h0, l0);
            split2(x1, h1, l1);
            *(__half2*)(g_zh + rowo + d0) = __halves2half2(h0, h1);
            *(__half2*)(g_zl + rowo + d0) = __halves2half2(l0, l1);
        }
    }
    #pragma unroll
    for (int o = 16; o > 0; o >>= 1) zacc += __shfl_xor_sync(0xffffffffu, zacc, o);
    if (lane == 0) zred[grp] = zacc;
    __syncthreads();
    if (tid == 0) {
        float t = 0.f;
        #pragma unroll
        for (int i = 0; i < 8; ++i) t += zred[i];
        g_zpart[blockIdx.x] = t;
    }
}

// ---------------------------------------------------------------------------
// K3: 1-term fp16 coarse GEMM + top2-argmin + flag + loss + fused Q-gather.
// grid=256 CTAs (128 tokens), block=512 (16 warps: 4M x 4N), warp 32x64.
// ---------------------------------------------------------------------------
#define RSTR    80
#define A_VST   (128 * RSTR)             // 10240
#define CB_BASE A_VST                    // coarse: B right after single A
#define CSTAGE  (A_VST + 256 * RSTR)     // 30720
#define CSMIN_O  (3 * CSTAGE)            // 92160
#define CSMINI_O (CSMIN_O + 2048)
#define CSMIN2_O (CSMINI_O + 2048)
#define CCNS_O   (CSMIN2_O + 2048)
#define CSMEM_TOTAL (CCNS_O + 4096)      // 102400

__global__ __launch_bounds__(512, 1)
void k_argmin_mma(const float* __restrict__ cb, float* __restrict__ out) {
    extern __shared__ char smem[];
    const uint32_t sb = smem_u32(smem);

    const int tid   = threadIdx.x;
    const int lane  = tid & 31;
    const int wid   = tid >> 5;
    const int warpM = wid & 3;
    const int warpN = wid >> 2;
    const int gid   = lane >> 2;
    const int tq    = lane & 3;
    const int tok0  = blockIdx.x * 128;

    float acc[2][8][4];
    #pragma unroll
    for (int mt = 0; mt < 2; ++mt)
        #pragma unroll
        for (int nt = 0; nt < 8; ++nt)
            #pragma unroll
            for (int c = 0; c < 4; ++c) acc[mt][nt][c] = 0.f;

    float v1[2][2], v2[2][2];
    int   i1[2][2];
    #pragma unroll
    for (int mt = 0; mt < 2; ++mt)
        #pragma unroll
        for (int h = 0; h < 2; ++h) { v1[mt][h] = 3.4e38f; v2[mt][h] = 3.4e38f; i1[mt][h] = 0; }

    const int a_row  = (lane & 15);
    const int a_coff = ((lane >> 4) & 1) * 16;
    const int b_row  = ((lane & 16) >> 1) + (lane & 7);
    const int b_coff = ((lane >> 3) & 1) * 16;

    float* cns = (float*)(smem + CCNS_O);
    cns[tid] = g_cnorm[tid];
    cns[tid + 512] = g_cnorm[tid + 512];

    auto stage_issue = [&](int cc, uint32_t sbase) {
        const int ct = cc >> 3;
        const int kc = cc & 7;
        {
            const int row = tid >> 2;
            const int q = tid & 3;
            cp16(sbase + row * RSTR + q * 16,
                 g_zh + (((size_t)(tok0 + row)) << 8) + kc * 32 + q * 8);
        }
        #pragma unroll
        for (int jj = 0; jj < 2; ++jj) {
            const int i = tid + jj * 512;
            const int row = i >> 2;
            const int q = i & 3;
            cp16(sbase + CB_BASE + row * RSTR + q * 16,
                 g_ch + (((size_t)(ct * 256 + row)) << 8) + kc * 32 + q * 8);
        }
        cp_commit();
    };

    stage_issue(0, sb);
    stage_issue(1, sb + CSTAGE);

    int sidx = 0;
    for (int cc = 0; cc < 32; ++cc) {
        if (cc < 31) cp_wait<1>(); else cp_wait<0>();
        __syncthreads();
        if (cc + 2 < 32) {
            int nidx = sidx + 2; if (nidx >= 3) nidx -= 3;
            stage_issue(cc + 2, sb + nidx * CSTAGE);
        }

        const uint32_t abase = sb + sidx * CSTAGE;
        const uint32_t bbase = abase + CB_BASE;

        #pragma unroll
        for (int kg = 0; kg < 2; ++kg) {
            uint32_t ah[2][4];
            #pragma unroll
            for (int mt = 0; mt < 2; ++mt) {
                const uint32_t ar = (warpM * 32 + mt * 16 + a_row) * RSTR + kg * 32 + a_coff;
                ldm_x4(ah[mt][0], ah[mt][1], ah[mt][2], ah[mt][3], abase + ar);
            }
            #pragma unroll
            for (int p = 0; p < 4; ++p) {
                const uint32_t br = (warpN * 64 + p * 16 + b_row) * RSTR + kg * 32 + b_coff;
                uint32_t b0, b1, b2, b3;
                ldm_x4(b0, b1, b2, b3, bbase + br);
                #pragma unroll
                for (int mt = 0; mt < 2; ++mt) {
                    mma_f16(acc[mt][2 * p],     ah[mt], b0, b1);
                    mma_f16(acc[mt][2 * p + 1], ah[mt], b2, b3);
                }
            }
        }

        if ((cc & 7) == 7) {
            const int ct = cc >> 3;
            #pragma unroll
            for (int mt = 0; mt < 2; ++mt) {
                #pragma unroll
                for (int nt = 0; nt < 8; ++nt) {
                    const int n0 = ct * 256 + warpN * 64 + nt * 8 + 2 * tq;
                    const float cn0 = cns[n0];
                    const float cn1 = cns[n0 + 1];
                    const float sc[2][2] = {
                        { fmaf(-2.f, acc[mt][nt][0], cn0), fmaf(-2.f, acc[mt][nt][1], cn1) },
                        { fmaf(-2.f, acc[mt][nt][2], cn0), fmaf(-2.f, acc[mt][nt][3], cn1) } };
                    #pragma unroll
                    for (int h = 0; h < 2; ++h) {
                        #pragma unroll
                        for (int c = 0; c < 2; ++c) {
                            const float s = sc[h][c];
                            if (s < v1[mt][h]) { v2[mt][h] = v1[mt][h]; v1[mt][h] = s; i1[mt][h] = n0 + c; }
                            else if (s < v2[mt][h]) v2[mt][h] = s;
                        }
                    }
                    acc[mt][nt][0] = acc[mt][nt][1] = acc[mt][nt][2] = acc[mt][nt][3] = 0.f;
                }
            }
        }
        if (++sidx >= 3) sidx -= 3;
    }

    float* sminv  = (float*)(smem + CSMIN_O);
    int*   smini  = (int*)(smem + CSMINI_O);
    float* sminv2 = (float*)(smem + CSMIN2_O);
    #pragma unroll
    for (int mt = 0; mt < 2; ++mt) {
        #pragma unroll
        for (int h = 0; h < 2; ++h) {
            float a1 = v1[mt][h], a2 = v2[mt][h];
            int   ai = i1[mt][h];
            #pragma unroll
            for (int off = 1; off <= 2; off <<= 1) {
                const float b1 = __shfl_xor_sync(0xffffffffu, a1, off);
                const int   bi = __shfl_xor_sync(0xffffffffu, ai, off);
                const float b2 = __shfl_xor_sync(0xffffffffu, a2, off);
                float loser;
                if (b1 < a1 || (b1 == a1 && bi < ai)) { loser = a1; a1 = b1; ai = bi; }
                else loser = b1;
                a2 = fminf(loser, fminf(a2, b2));
            }
            if (tq == 0) {
                const int row = warpM * 32 + mt * 16 + h * 8 + gid;
                sminv [warpN * 128 + row] = a1;
                smini [warpN * 128 + row] = ai;
                sminv2[warpN * 128 + row] = a2;
            }
        }
    }
    __syncthreads();

    if (tid < 128) {
        float a1 = sminv[tid], a2 = sminv2[tid];
        int   ai = smini[tid];
        #pragma unroll
        for (int wn = 1; wn < 4; ++wn) {
            const float b1 = sminv[wn * 128 + tid];
            const int   bi = smini[wn * 128 + tid];
            const float b2 = sminv2[wn * 128 + tid];
            float loser;
            if (b1 < a1 || (b1 == a1 && bi < ai)) { loser = a1; a1 = b1; ai = bi; }
            else loser = b1;
            a2 = fminf(loser, fminf(a2, b2));
        }
        const int tok = tok0 + tid;
        g_idx[tok] = ai;
        atomicAdd(&g_counts[ai], 1);
        if (a2 - a1 < EPS_AMBIG) {
            const int pos = atomicAdd(&g_flagcnt, 1);
            g_flaglist[pos] = tok;
        }
        float sum = a1;
        #pragma unroll
        for (int o = 16; o > 0; o >>= 1) sum += __shfl_xor_sync(0xffffffffu, sum, o);
        if (lane == 0) cns[wid] = sum;
        smini[tid] = ai;
    }
    __syncthreads();
    if (tid == 0)
        g_minpart[blockIdx.x] = (cns[0] + cns[1]) + (cns[2] + cns[3]);

    // fused quantized-output gather (coarse idx; recheck fixes rare flips)
    {
        float* cshare = (float*)smem;
        const int b   = tok0 >> 10;
        const int hw0 = tok0 & 1023;
        const int w   = tid >> 5;
        #pragma unroll
        for (int g = 0; g < 4; ++g) {
            #pragma unroll
            for (int j = 0; j < 4; ++j) {
                const int slot = tid + j * 512;
                const int row  = slot >> 6;
                const int q    = slot & 63;
                const float4 v = __ldg((const float4*)(cb + (size_t)smini[g * 32 + row] * DIM) + q);
                float* cd = cshare + row * 257 + q * 4;
                cd[0] = v.x; cd[1] = v.y; cd[2] = v.z; cd[3] = v.w;
            }
            __syncthreads();
            float* qbase = out + OFF_Q + (size_t)b * DIM * HWSZ + hw0 + g * 32 + lane;
            #pragma unroll
            for (int dd = 0; dd < 16; ++dd) {
                const int d = w + dd * 16;
                qbase[(size_t)d * HWSZ] = cshare[lane * 257 + d];
            }
            __syncthreads();
        }
    }
}

// ---------------------------------------------------------------------------
// K4: MMA-based exact recheck. Grid-strided tiles of 128 flagged tokens,
// 3-term fp16 (hh + hl + lh) over all 1024 codes; fixes idx/counts/Q rows.
// block=512 (16 warps: 4M x 4N); same pipeline as the R12 main GEMM.
// ---------------------------------------------------------------------------
#define RB_BASE (2 * A_VST)              // 20480 (A: zh,zl gathered)
#define RSTAGE  (RB_BASE + 2 * 256 * RSTR) // 61440
#define RSMIN_O  (3 * RSTAGE)            // 184320
#define RSMINI_O (RSMIN_O + 2048)
#define RCNS_O   (RSMINI_O + 2048)
#define RFLG_O   (RCNS_O + 4096)         // 192512: int[128] flag toks + int[128] newidx
#define RSMEM_TOTAL (RFLG_O + 1024)      // 193536

__global__ __launch_bounds__(512, 1)
void k_recheck(const float* __restrict__ cb, float* __restrict__ out) {
    extern __shared__ char smem[];
    const uint32_t sb = smem_u32(smem);

    const int tid   = threadIdx.x;
    const int lane  = tid & 31;
    const int wid   = tid >> 5;
    const int warpM = wid & 3;
    const int warpN = wid >> 2;
    const int gid   = lane >> 2;
    const int tq    = lane & 3;
    const int cnt   = g_flagcnt;

    const int a_row  = (lane & 15);
    const int a_coff = ((lane >> 4) & 1) * 16;
    const int b_row  = ((lane & 16) >> 1) + (lane & 7);
    const int b_coff = ((lane >> 3) & 1) * 16;

    float* cns   = (float*)(smem + RCNS_O);
    int*   ftok  = (int*)(smem + RFLG_O);
    int*   fnew  = ftok + 128;
    float* sminv = (float*)(smem + RSMIN_O);
    int*   smini = (int*)(smem + RSMINI_O);

    cns[tid] = g_cnorm[tid];
    cns[tid + 512] = g_cnorm[tid + 512];

    for (int tile = blockIdx.x; tile * 128 < cnt; tile += gridDim.x) {
        const int base = tile * 128;
        const int nt = min(128, cnt - base);
        if (tid < 128) ftok[tid] = g_flaglist[base + min(tid, nt - 1)];
        __syncthreads();

        float acc[2][8][4];
        #pragma unroll
        for (int mt = 0; mt < 2; ++mt)
            #pragma unroll
            for (int ntl = 0; ntl < 8; ++ntl)
                #pragma unroll
                for (int c = 0; c < 4; ++c) acc[mt][ntl][c] = 0.f;
        float v1[2][2];
        int   i1[2][2];
        #pragma unroll
        for (int mt = 0; mt < 2; ++mt)
            #pragma unroll
            for (int h = 0; h < 2; ++h) { v1[mt][h] = 3.4e38f; i1[mt][h] = 0; }

        auto stage_issue = [&](int cc, uint32_t sbase) {
            const int ct = cc >> 3;
            const int kc = cc & 7;
            #pragma unroll
            for (int jj = 0; jj < 2; ++jj) {       // A: gathered zh,zl (1024 slots)
                const int i = tid * 2 + jj;
                const int v = i >> 9;
                const int row = (i >> 2) & 127;
                const int q = i & 3;
                const __half* src = (v ? g_zl : g_zh) + (((size_t)ftok[row]) << 8) + kc * 32 + q * 8;
                cp16(sbase + v * A_VST + row * RSTR + q * 16, src);
            }
            #pragma unroll
            for (int jj = 0; jj < 4; ++jj) {       // B: ch,cl (2048 slots)
                const int i = tid + jj * 512;
                const int v = i >> 10;
                const int row = (i >> 2) & 255;
                const int q = i & 3;
                const __half* src = (v ? g_cl : g_ch) + (((size_t)(ct * 256 + row)) << 8) + kc * 32 + q * 8;
                cp16(sbase + RB_BASE + v * (256 * RSTR) + row * RSTR + q * 16, src);
            }
            cp_commit();
        };

        stage_issue(0, sb);
        stage_issue(1, sb + RSTAGE);

        int sidx = 0;
        for (int cc = 0; cc < 32; ++cc) {
            if (cc < 31) cp_wait<1>(); else cp_wait<0>();
            __syncthreads();
            if (cc + 2 < 32) {
                int nidx = sidx + 2; if (nidx >= 3) nidx -= 3;
                stage_issue(cc + 2, sb + nidx * RSTAGE);
            }

            const uint32_t abase = sb + sidx * RSTAGE;
            const uint32_t bbase = abase + RB_BASE;

            #pragma unroll
            for (int kg = 0; kg < 2; ++kg) {
                uint32_t ah[2][4], al[2][4];
                #pragma unroll
                for (int mt = 0; mt < 2; ++mt) {
                    const uint32_t ar = (warpM * 32 + mt * 16 + a_row) * RSTR + kg * 32 + a_coff;
                    ldm_x4(ah[mt][0], ah[mt][1], ah[mt][2], ah[mt][3], abase + ar);
                    ldm_x4(al[mt][0], al[mt][1], al[mt][2], al[mt][3], abase + A_VST + ar);
                }
                #pragma unroll
                for (int p = 0; p < 4; ++p) {
                    const uint32_t br = (warpN * 64 + p * 16 + b_row) * RSTR + kg * 32 + b_coff;
                    uint32_t b0, b1, b2, b3;
                    ldm_x4(b0, b1, b2, b3, bbase + br);
                    #pragma unroll
                    for (int mt = 0; mt < 2; ++mt) {
                        mma_f16(acc[mt][2 * p],     ah[mt], b0, b1);
                        mma_f16(acc[mt][2 * p + 1], ah[mt], b2, b3);
                    }
                    #pragma unroll
                    for (int mt = 0; mt < 2; ++mt) {
                        mma_f16(acc[mt][2 * p],     al[mt], b0, b1);
                        mma_f16(acc[mt][2 * p + 1], al[mt], b2, b3);
                    }
                    ldm_x4(b0, b1, b2, b3, bbase + 256 * RSTR + br);
                    #pragma unroll
                    for (int mt = 0; mt < 2; ++mt) {
                        mma_f16(acc[mt][2 * p],     ah[mt], b0, b1);
                        mma_f16(acc[mt][2 * p + 1], ah[mt], b2, b3);
                    }
                }
            }

            if ((cc & 7) == 7) {
                const int ct = cc >> 3;
                #pragma unroll
                for (int mt = 0; mt < 2; ++mt) {
                    #pragma unroll
                    for (int ntl = 0; ntl < 8; ++ntl) {
                        const int n0 = ct * 256 + warpN * 64 + ntl * 8 + 2 * tq;
                        const float cn0 = cns[n0];
                        const float cn1 = cns[n0 + 1];
                        const float s00 = fmaf(-2.f, acc[mt][ntl][0], cn0);
                        const float s01 = fmaf(-2.f, acc[mt][ntl][1], cn1);
                        const float s10 = fmaf(-2.f, acc[mt][ntl][2], cn0);
                        const float s11 = fmaf(-2.f, acc[mt][ntl][3], cn1);
                        if (s00 < v1[mt][0]) { v1[mt][0] = s00; i1[mt][0] = n0; }
                        if (s01 < v1[mt][0]) { v1[mt][0] = s01; i1[mt][0] = n0 + 1; }
                        if (s10 < v1[mt][1]) { v1[mt][1] = s10; i1[mt][1] = n0; }
                        if (s11 < v1[mt][1]) { v1[mt][1] = s11; i1[mt][1] = n0 + 1; }
                        acc[mt][ntl][0] = acc[mt][ntl][1] = acc[mt][ntl][2] = acc[mt][ntl][3] = 0.f;
                    }
                }
            }
            if (++sidx >= 3) sidx -= 3;
        }

        #pragma unroll
        for (int mt = 0; mt < 2; ++mt) {
            #pragma unroll
            for (int h = 0; h < 2; ++h) {
                float v  = v1[mt][h];
                int   ix = i1[mt][h];
                #pragma unroll
                for (int off = 1; off <= 2; off <<= 1) {
                    const float ov = __shfl_xor_sync(0xffffffffu, v, off);
                    const int   oi = __shfl_xor_sync(0xffffffffu, ix, off);
                    if (ov < v || (ov == v && oi < ix)) { v = ov; ix = oi; }
                }
                if (tq == 0) {
                    const int row = warpM * 32 + mt * 16 + h * 8 + gid;
                    sminv[warpN * 128 + row] = v;
                    smini[warpN * 128 + row] = ix;
                }
            }
        }
        __syncthreads();

        if (tid < 128) {
            float v = sminv[tid];
            int   i = smini[tid];
            #pragma unroll
            for (int wn = 1; wn < 4; ++wn) {
                const float ov = sminv[wn * 128 + tid];
                const int   oi = smini[wn * 128 + tid];
                if (ov < v || (ov == v && oi < i)) { v = ov; i = oi; }
            }
            int flip = -1;
            if (tid < nt) {
                const int tok = ftok[tid];
                const int old = g_idx[tok];
                if (i != old) {
                    atomicSub(&g_counts[old], 1);
                    atomicAdd(&g_counts[i], 1);
                    g_idx[tok] = i;
                    flip = i;
                }
            }
            fnew[tid] = flip;
        }
        __syncthreads();

        // rewrite Q rows for flipped tokens (rare)
        for (int r = 0; r < nt; ++r) {
            const int ni = fnew[r];
            if (ni >= 0 && tid < 256) {
                const int tok = ftok[r];
                const int b = tok >> 10, hw = tok & 1023;
                out[OFF_Q + (size_t)b * DIM * HWSZ + (size_t)tid * HWSZ + hw] =
                    __ldg(cb + (size_t)ni * DIM + tid);
            }
        }
        __syncthreads();
    }
}

// ---------------------------------------------------------------------------
// K5: offsets scan + EMA + perplexity + loss. 1 block, 1024 threads
// ---------------------------------------------------------------------------
__global__ void k_offfin(const float* __restrict__ ema_cs, float* __restrict__ out) {
    __shared__ int   sc[NUM_K];
    __shared__ float red[32];
    __shared__ float nsh, zsh;
    const int t = threadIdx.x;
    const int c = g_counts[t];

    sc[t] = c;
    __syncthreads();
    for (int off = 1; off < NUM_K; off <<= 1) {
        const int v = (t >= off) ? sc[t - off] : 0;
        __syncthreads();
        sc[t] += v;
        __syncthreads();
    }
    const int excl = sc[t] - c;
    g_off[t] = excl;
    g_cur[t] = excl;

    float zs = g_zpart[t] + ((t < 256) ? g_minpart[t] : 0.f);
    #pragma unroll
    for (int o = 16; o > 0; o >>= 1) zs += __shfl_xor_sync(0xffffffffu, zs, o);
    if ((t & 31) == 0) red[t >> 5] = zs;
    __syncthreads();
    if (t < 32) {
        float x = red[t];
        #pragma unroll
        for (int o = 16; o > 0; o >>= 1) x += __shfl_xor_sync(0xffffffffu, x, o);
        if (t == 0) zsh = x;
    }
    __syncthreads();

    const float cnt = (float)c;
    const float ncs = ema_cs[t] * DECAYF + OMD * cnt;
    out[OFF_CS + t] = ncs;

    float s = ncs;
    #pragma unroll
    for (int o = 16; o > 0; o >>= 1) s += __shfl_xor_sync(0xffffffffu, s, o);
    if ((t & 31) == 0) red[t >> 5] = s;
    __syncthreads();
    if (t < 32) {
        float x = red[t];
        #pragma unroll
        for (int o = 16; o > 0; o >>= 1) x += __shfl_xor_sync(0xffffffffu, x, o);
        if (t == 0) nsh = x;
    }
    __syncthreads();
    const float n = nsh;
    g_csadj[t] = (ncs + EPSF) / (n + NUM_K * EPSF) * n;

    const float p = cnt / (float)NTOK;
    float s2 = p * logf(p + 1e-10f);
    #pragma unroll
    for (int o = 16; o > 0; o >>= 1) s2 += __shfl_xor_sync(0xffffffffu, s2, o);
    if ((t & 31) == 0) red[t >> 5] = s2;
    __syncthreads();
    if (t == 0) {
        float x = 0.f;
        #pragma unroll
        for (int i = 0; i < 32; i++) x += red[i];
        out[OFF_PERP] = expf(-x);
        out[OFF_LOSS] = CCOST * zsh / (float)(NTOK * DIM);
    }
}

// ---------------------------------------------------------------------------
// K6: bucket tokens by code. grid=128, block=256
// ---------------------------------------------------------------------------
__global__ void k_bucket() {
    const int tok = blockIdx.x * 256 + threadIdx.x;
    const int k = g_idx[tok];
    const int pos = atomicAdd(&g_cur[k], 1);
    g_toklist[pos] = tok;
}

// ---------------------------------------------------------------------------
// K7: dw gather (smem token list) + EMA + codebook division. grid=1024, block=256
// ---------------------------------------------------------------------------
#define MAXB 128
__global__ __launch_bounds__(256)
void k_dwfin(const float* __restrict__ ema_dw, float* __restrict__ out) {
    __shared__ int stok[MAXB];
    const int k = blockIdx.x;
    const int d = threadIdx.x;
    const int start = g_off[k];
    const int cnt   = g_counts[k];

    for (int i = d; i < cnt && i < MAXB; i += 256) stok[i] = g_toklist[start + i];
    __syncthreads();

    float acc = 0.f;
    const int csmem = (cnt < MAXB) ? cnt : MAXB;
    int i = 0;
    for (; i + 4 <= csmem; i += 4) {
        const int t0 = stok[i], t1 = stok[i + 1], t2 = stok[i + 2], t3 = stok[i + 3];
        const float v0 = __half2float(g_zh[((size_t)t0 << 8) + d]) + __half2float(g_zl[((size_t)t0 << 8) + d]);
        const float v1 = __half2float(g_zh[((size_t)t1 << 8) + d]) + __half2float(g_zl[((size_t)t1 << 8) + d]);
        const float v2 = __half2float(g_zh[((size_t)t2 << 8) + d]) + __half2float(g_zl[((size_t)t2 << 8) + d]);
        const float v3 = __half2float(g_zh[((size_t)t3 << 8) + d]) + __half2float(g_zl[((size_t)t3 << 8) + d]);
        acc += (v0 + v1) + (v2 + v3);
    }
    for (; i < csmem; ++i) {
        const size_t o = ((size_t)stok[i] << 8) + d;
        acc += __half2float(g_zh[o]) + __half2float(g_zl[o]);
    }
    for (int j = MAXB; j < cnt; ++j) {
        const size_t o = ((size_t)g_toklist[start + j] << 8) + d;
        acc += __half2float(g_zh[o]) + __half2float(g_zl[o]);
    }

    const size_t o = (size_t)k * DIM + d;
    const float nd = ema_dw[o] * DECAYF + OMD * acc;
    out[OFF_EDW + o] = nd;
    out[OFF_CB  + o] = nd / g_csadj[k];
}

// ---------------------------------------------------------------------------
extern "C" void kernel_launch(void* const* d_in, const int* in_sizes, int n_in,
                              void* d_out, int out_size) {
    const float* z      = (const float*)d_in[0];
    const float* cb     = (const float*)d_in[1];
    const float* ema_cs = (const float*)d_in[2];
    const float* ema_dw = (const float*)d_in[3];
    float* out = (float*)d_out;

    cudaFuncSetAttribute(k_argmin_mma, cudaFuncAttributeMaxDynamicSharedMemorySize, CSMEM_TOTAL);
    cudaFuncSetAttribute(k_recheck,    cudaFuncAttributeMaxDynamicSharedMemorySize, RSMEM_TOTAL);

    k_init<<<NUM_K, 64>>>(cb);
    k_zsplit<<<1024, 256>>>(z);
    k_argmin_mma<<<NTOK / 128, 512, CSMEM_TOTAL>>>(cb, out);
    k_recheck<<<16, 512, RSMEM_TOTAL>>>(cb, out);     // profiled slot 4
    k_offfin<<<1, 1024>>>(ema_cs, out);
    k_bucket<<<NTOK / 256, 256>>>();
    k_dwfin<<<NUM_K, 256>>>(ema_dw, out);
}

// round 16
// speedup vs baseline: 1.2466x; 1.1970x over previous
#include <cuda_runtime.h>
#include <cuda_fp16.h>
#include <math.h>
#include <stdint.h>

// Problem constants
#define NUM_K  1024
#define DIM    256
#define HWSZ   1024
#define NTOK   32768
#define DECAYF 0.99f
#define OMD    0.01f
#define CCOST  0.25f
#define EPSF   1e-5f
#define EPS_AMBIG 0.08f

// Output layout
#define OFF_Q    0
#define OFF_LOSS 8388608
#define OFF_PERP 8388609
#define OFF_CB   8388610
#define OFF_CS   8650754
#define OFF_EDW  8651778

// Scratch
__device__ float g_cnorm[NUM_K];
__device__ int   g_counts[NUM_K];
__device__ int   g_idx[NTOK];
__device__ float g_zpart[1024];
__device__ float g_minpart[256];
__device__ float g_csadj[NUM_K];
__device__ int   g_off[NUM_K];
__device__ int   g_cur[NUM_K];
__device__ int   g_toklist[NTOK];
__device__ int   g_flagcnt;
__device__ int   g_flaglist[NTOK];
__device__ int   g_flipcnt;
__device__ int   g_fliplist[NTOK];
__device__ unsigned long long g_best[NTOK];

// fp16 splits (token-major / code-major, 256 cols, K contiguous)
__device__ __align__(16) __half g_zh[NTOK * DIM];
__device__ __align__(16) __half g_zl[NTOK * DIM];
__device__ __align__(16) __half g_ch[NUM_K * DIM];
__device__ __align__(16) __half g_cl[NUM_K * DIM];

__device__ __forceinline__ void split2(float x, __half& h, __half& l) {
    h = __float2half_rn(x);
    l = __float2half_rn(x - __half2float(h));
}
__device__ __forceinline__ uint32_t smem_u32(const void* p) {
    uint32_t a;
    asm("{ .reg .u64 t; cvta.to.shared.u64 t, %1; cvt.u32.u64 %0, t; }" : "=r"(a) : "l"(p));
    return a;
}
__device__ __forceinline__ void ldm_x4(uint32_t& r0, uint32_t& r1, uint32_t& r2, uint32_t& r3, uint32_t addr) {
    asm volatile("ldmatrix.sync.aligned.m8n8.x4.shared.b16 {%0,%1,%2,%3}, [%4];"
                 : "=r"(r0), "=r"(r1), "=r"(r2), "=r"(r3) : "r"(addr));
}
__device__ __forceinline__ void mma_f16(float* c, const uint32_t* a, uint32_t b0, uint32_t b1) {
    asm volatile("mma.sync.aligned.m16n8k16.row.col.f32.f16.f16.f32 "
                 "{%0,%1,%2,%3}, {%4,%5,%6,%7}, {%8,%9}, {%0,%1,%2,%3};"
                 : "+f"(c[0]), "+f"(c[1]), "+f"(c[2]), "+f"(c[3])
                 : "r"(a[0]), "r"(a[1]), "r"(a[2]), "r"(a[3]), "r"(b0), "r"(b1));
}
__device__ __forceinline__ void cp16(uint32_t dst, const void* src) {
    asm volatile("cp.async.cg.shared.global [%0], [%1], 16;" :: "r"(dst), "l"(src));
}
__device__ __forceinline__ void cp_commit() { asm volatile("cp.async.commit_group;" ::: "memory"); }
template<int N> __device__ __forceinline__ void cp_wait() {
    asm volatile("cp.async.wait_group %0;" :: "n"(N) : "memory");
}
// order-preserving (score, idx) packing: smaller packed == (smaller score, then smaller idx)
__device__ __forceinline__ unsigned long long pack_si(float s, int idx) {
    uint32_t u = __float_as_uint(s);
    u = (u & 0x80000000u) ? ~u : (u | 0x80000000u);
    return ((unsigned long long)u << 32) | (unsigned)idx;
}

// ---------------------------------------------------------------------------
// K1: codebook norms + fp16 splits (hi+lo) + clears. grid=1024, block=64
// ---------------------------------------------------------------------------
__global__ void k_init(const float* __restrict__ cb) {
    const int k = blockIdx.x;
    const int t = threadIdx.x;
    const float4 c4 = ((const float4*)(cb + k * DIM))[t];
    float s = c4.x * c4.x + c4.y * c4.y + c4.z * c4.z + c4.w * c4.w;
    #pragma unroll
    for (int o = 16; o > 0; o >>= 1) s += __shfl_xor_sync(0xffffffffu, s, o);
    __shared__ float red[2];
    if ((t & 31) == 0) red[t >> 5] = s;
    #pragma unroll
    for (int j = 0; j < 4; j++) {
        const int d = t + 64 * j;
        __half h, l;
        split2(cb[k * DIM + d], h, l);
        g_ch[k * DIM + d] = h;
        g_cl[k * DIM + d] = l;
    }
    __syncthreads();
    if (t == 0) {
        g_cnorm[k]  = red[0] + red[1];
        g_counts[k] = 0;
        if (k == 0) { g_flagcnt = 0; g_flipcnt = 0; }
    }
}

// ---------------------------------------------------------------------------
// K2: transpose + fp16-split z + ||z||^2 partial. grid=1024, block=256
// ---------------------------------------------------------------------------
__global__ __launch_bounds__(256)
void k_zsplit(const float* __restrict__ z) {
    __shared__ float s[256][33];
    __shared__ float zred[8];
    const int b    = blockIdx.x >> 5;
    const int hwc  = blockIdx.x & 31;
    const int tid  = threadIdx.x;
    const int lane = tid & 31;
    const int grp  = tid >> 5;

    const float* zb = z + (size_t)b * DIM * HWSZ + hwc * 32;
    #pragma unroll 8
    for (int dd = 0; dd < 32; ++dd) {
        const int d = grp * 32 + dd;
        s[d][lane] = zb[(size_t)d * HWSZ + lane];
    }
    __syncthreads();

    float zacc = 0.f;
    #pragma unroll
    for (int tg = 0; tg < 4; ++tg) {
        const int tok = tg * 8 + grp;
        const size_t rowo = ((size_t)(b * HWSZ + hwc * 32 + tok)) * DIM;
        #pragma unroll
        for (int j = 0; j < 4; ++j) {
            const int d0 = (j * 32 + lane) * 2;
            const float x0 = s[d0][tok];
            const float x1 = s[d0 + 1][tok];
            zacc = fmaf(x0, x0, zacc);
            zacc = fmaf(x1, x1, zacc);
            __half h0, l0, h1, l1;
            split2(x0, h0, l0);
            split2(x1, h1, l1);
            *(__half2*)(g_zh + rowo + d0) = __halves2half2(h0, h1);
            *(__half2*)(g_zl + rowo + d0) = __halves2half2(l0, l1);
        }
    }
    #pragma unroll
    for (int o = 16; o > 0; o >>= 1) zacc += __shfl_xor_sync(0xffffffffu, zacc, o);
    if (lane == 0) zred[grp] = zacc;
    __syncthreads();
    if (tid == 0) {
        float t = 0.f;
        #pragma unroll
        for (int i = 0; i < 8; ++i) t += zred[i];
        g_zpart[blockIdx.x] = t;
    }
}

// ---------------------------------------------------------------------------
// K3: 1-term fp16 coarse GEMM + top2-argmin + flag + loss + fused Q-gather.
// grid=256 CTAs (128 tokens), block=512 (16 warps: 4M x 4N), warp 32x64.
// ---------------------------------------------------------------------------
#define RSTR    80
#define A_VST   (128 * RSTR)             // 10240
#define CB_BASE A_VST
#define CSTAGE  (A_VST + 256 * RSTR)     // 30720
#define CSMIN_O  (3 * CSTAGE)            // 92160
#define CSMINI_O (CSMIN_O + 2048)
#define CSMIN2_O (CSMINI_O + 2048)
#define CCNS_O   (CSMIN2_O + 2048)
#define CSMEM_TOTAL (CCNS_O + 4096)      // 102400

__global__ __launch_bounds__(512, 1)
void k_argmin_mma(const float* __restrict__ cb, float* __restrict__ out) {
    extern __shared__ char smem[];
    const uint32_t sb = smem_u32(smem);

    const int tid   = threadIdx.x;
    const int lane  = tid & 31;
    const int wid   = tid >> 5;
    const int warpM = wid & 3;
    const int warpN = wid >> 2;
    const int gid   = lane >> 2;
    const int tq    = lane & 3;
    const int tok0  = blockIdx.x * 128;

    float acc[2][8][4];
    #pragma unroll
    for (int mt = 0; mt < 2; ++mt)
        #pragma unroll
        for (int nt = 0; nt < 8; ++nt)
            #pragma unroll
            for (int c = 0; c < 4; ++c) acc[mt][nt][c] = 0.f;

    float v1[2][2], v2[2][2];
    int   i1[2][2];
    #pragma unroll
    for (int mt = 0; mt < 2; ++mt)
        #pragma unroll
        for (int h = 0; h < 2; ++h) { v1[mt][h] = 3.4e38f; v2[mt][h] = 3.4e38f; i1[mt][h] = 0; }

    const int a_row  = (lane & 15);
    const int a_coff = ((lane >> 4) & 1) * 16;
    const int b_row  = ((lane & 16) >> 1) + (lane & 7);
    const int b_coff = ((lane >> 3) & 1) * 16;

    float* cns = (float*)(smem + CCNS_O);
    cns[tid] = g_cnorm[tid];
    cns[tid + 512] = g_cnorm[tid + 512];

    auto stage_issue = [&](int cc, uint32_t sbase) {
        const int ct = cc >> 3;
        const int kc = cc & 7;
        {
            const int row = tid >> 2;
            const int q = tid & 3;
            cp16(sbase + row * RSTR + q * 16,
                 g_zh + (((size_t)(tok0 + row)) << 8) + kc * 32 + q * 8);
        }
        #pragma unroll
        for (int jj = 0; jj < 2; ++jj) {
            const int i = tid + jj * 512;
            const int row = i >> 2;
            const int q = i & 3;
            cp16(sbase + CB_BASE + row * RSTR + q * 16,
                 g_ch + (((size_t)(ct * 256 + row)) << 8) + kc * 32 + q * 8);
        }
        cp_commit();
    };

    stage_issue(0, sb);
    stage_issue(1, sb + CSTAGE);

    int sidx = 0;
    for (int cc = 0; cc < 32; ++cc) {
        if (cc < 31) cp_wait<1>(); else cp_wait<0>();
        __syncthreads();
        if (cc + 2 < 32) {
            int nidx = sidx + 2; if (nidx >= 3) nidx -= 3;
            stage_issue(cc + 2, sb + nidx * CSTAGE);
        }

        const uint32_t abase = sb + sidx * CSTAGE;
        const uint32_t bbase = abase + CB_BASE;

        #pragma unroll
        for (int kg = 0; kg < 2; ++kg) {
            uint32_t ah[2][4];
            #pragma unroll
            for (int mt = 0; mt < 2; ++mt) {
                const uint32_t ar = (warpM * 32 + mt * 16 + a_row) * RSTR + kg * 32 + a_coff;
                ldm_x4(ah[mt][0], ah[mt][1], ah[mt][2], ah[mt][3], abase + ar);
            }
            #pragma unroll
            for (int p = 0; p < 4; ++p) {
                const uint32_t br = (warpN * 64 + p * 16 + b_row) * RSTR + kg * 32 + b_coff;
                uint32_t b0, b1, b2, b3;
                ldm_x4(b0, b1, b2, b3, bbase + br);
                #pragma unroll
                for (int mt = 0; mt < 2; ++mt) {
                    mma_f16(acc[mt][2 * p],     ah[mt], b0, b1);
                    mma_f16(acc[mt][2 * p + 1], ah[mt], b2, b3);
                }
            }
        }

        if ((cc & 7) == 7) {
            const int ct = cc >> 3;
            #pragma unroll
            for (int mt = 0; mt < 2; ++mt) {
                #pragma unroll
                for (int nt = 0; nt < 8; ++nt) {
                    const int n0 = ct * 256 + warpN * 64 + nt * 8 + 2 * tq;
                    const float cn0 = cns[n0];
                    const float cn1 = cns[n0 + 1];
                    const float sc[2][2] = {
                        { fmaf(-2.f, acc[mt][nt][0], cn0), fmaf(-2.f, acc[mt][nt][1], cn1) },
                        { fmaf(-2.f, acc[mt][nt][2], cn0), fmaf(-2.f, acc[mt][nt][3], cn1) } };
                    #pragma unroll
                    for (int h = 0; h < 2; ++h) {
                        #pragma unroll
                        for (int c = 0; c < 2; ++c) {
                            const float s = sc[h][c];
                            if (s < v1[mt][h]) { v2[mt][h] = v1[mt][h]; v1[mt][h] = s; i1[mt][h] = n0 + c; }
                            else if (s < v2[mt][h]) v2[mt][h] = s;
                        }
                    }
                    acc[mt][nt][0] = acc[mt][nt][1] = acc[mt][nt][2] = acc[mt][nt][3] = 0.f;
                }
            }
        }
        if (++sidx >= 3) sidx -= 3;
    }

    float* sminv  = (float*)(smem + CSMIN_O);
    int*   smini  = (int*)(smem + CSMINI_O);
    float* sminv2 = (float*)(smem + CSMIN2_O);
    #pragma unroll
    for (int mt = 0; mt < 2; ++mt) {
        #pragma unroll
        for (int h = 0; h < 2; ++h) {
            float a1 = v1[mt][h], a2 = v2[mt][h];
            int   ai = i1[mt][h];
            #pragma unroll
            for (int off = 1; off <= 2; off <<= 1) {
                const float b1 = __shfl_xor_sync(0xffffffffu, a1, off);
                const int   bi = __shfl_xor_sync(0xffffffffu, ai, off);
                const float b2 = __shfl_xor_sync(0xffffffffu, a2, off);
                float loser;
                if (b1 < a1 || (b1 == a1 && bi < ai)) { loser = a1; a1 = b1; ai = bi; }
                else loser = b1;
                a2 = fminf(loser, fminf(a2, b2));
            }
            if (tq == 0) {
                const int row = warpM * 32 + mt * 16 + h * 8 + gid;
                sminv [warpN * 128 + row] = a1;
                smini [warpN * 128 + row] = ai;
                sminv2[warpN * 128 + row] = a2;
            }
        }
    }
    __syncthreads();

    if (tid < 128) {
        float a1 = sminv[tid], a2 = sminv2[tid];
        int   ai = smini[tid];
        #pragma unroll
        for (int wn = 1; wn < 4; ++wn) {
            const float b1 = sminv[wn * 128 + tid];
            const int   bi = smini[wn * 128 + tid];
            const float b2 = sminv2[wn * 128 + tid];
            float loser;
            if (b1 < a1 || (b1 == a1 && bi < ai)) { loser = a1; a1 = b1; ai = bi; }
            else loser = b1;
            a2 = fminf(loser, fminf(a2, b2));
        }
        const int tok = tok0 + tid;
        g_idx[tok] = ai;
        atomicAdd(&g_counts[ai], 1);
        if (a2 - a1 < EPS_AMBIG) {
            const int pos = atomicAdd(&g_flagcnt, 1);
            g_flaglist[pos] = tok;
            g_best[tok] = 0xFFFFFFFFFFFFFFFFull;
        }
        float sum = a1;
        #pragma unroll
        for (int o = 16; o > 0; o >>= 1) sum += __shfl_xor_sync(0xffffffffu, sum, o);
        if (lane == 0) cns[wid] = sum;
        smini[tid] = ai;
    }
    __syncthreads();
    if (tid == 0)
        g_minpart[blockIdx.x] = (cns[0] + cns[1]) + (cns[2] + cns[3]);

    // fused quantized-output gather (coarse idx; offfin fixes rare flips)
    {
        float* cshare = (float*)smem;
        const int b   = tok0 >> 10;
        const int hw0 = tok0 & 1023;
        const int w   = tid >> 5;
        #pragma unroll
        for (int g = 0; g < 4; ++g) {
            #pragma unroll
            for (int j = 0; j < 4; ++j) {
                const int slot = tid + j * 512;
                const int row  = slot >> 6;
                const int q    = slot & 63;
                const float4 v = __ldg((const float4*)(cb + (size_t)smini[g * 32 + row] * DIM) + q);
                float* cd = cshare + row * 257 + q * 4;
                cd[0] = v.x; cd[1] = v.y; cd[2] = v.z; cd[3] = v.w;
            }
            __syncthreads();
            float* qbase = out + OFF_Q + (size_t)b * DIM * HWSZ + hw0 + g * 32 + lane;
            #pragma unroll
            for (int dd = 0; dd < 16; ++dd) {
                const int d = w + dd * 16;
                qbase[(size_t)d * HWSZ] = cshare[lane * 257 + d];
            }
            __syncthreads();
        }
    }
}

// ---------------------------------------------------------------------------
// K4: MMA exact recheck, parallel over (flag-tile x code-tile) work items.
// Each item: 128 gathered tokens x 256 codes, 3-term fp16, K=256 (8 chunks).
// Partial argmin merged via packed atomicMin into g_best.
// ---------------------------------------------------------------------------
#define RB_BASE (2 * A_VST)                // 20480
#define RSTAGE  (RB_BASE + 2 * 256 * RSTR) // 61440
#define RSMIN_O  (3 * RSTAGE)              // 184320
#define RSMINI_O (RSMIN_O + 2048)
#define RCNS_O   (RSMINI_O + 2048)
#define RFLG_O   (RCNS_O + 4096)
#define RSMEM_TOTAL (RFLG_O + 512)         // 193024

__global__ __launch_bounds__(512, 1)
void k_recheck() {
    extern __shared__ char smem[];
    const uint32_t sb = smem_u32(smem);

    const int tid   = threadIdx.x;
    const int lane  = tid & 31;
    const int wid   = tid >> 5;
    const int warpM = wid & 3;
    const int warpN = wid >> 2;
    const int gid   = lane >> 2;
    const int tq    = lane & 3;
    const int cnt   = g_flagcnt;
    const int nwork = ((cnt + 127) >> 7) * 4;

    const int a_row  = (lane & 15);
    const int a_coff = ((lane >> 4) & 1) * 16;
    const int b_row  = ((lane & 16) >> 1) + (lane & 7);
    const int b_coff = ((lane >> 3) & 1) * 16;

    float* cns   = (float*)(smem + RCNS_O);
    int*   ftok  = (int*)(smem + RFLG_O);
    float* sminv = (float*)(smem + RSMIN_O);
    int*   smini = (int*)(smem + RSMINI_O);

    cns[tid] = g_cnorm[tid];
    cns[tid + 512] = g_cnorm[tid + 512];

    for (int w = blockIdx.x; w < nwork; w += gridDim.x) {
        const int tile = w >> 2;
        const int ct   = w & 3;
        const int base = tile * 128;
        const int nt   = min(128, cnt - base);
        if (tid < 128) ftok[tid] = g_flaglist[base + min(tid, nt - 1)];
        __syncthreads();

        float acc[2][8][4];
        #pragma unroll
        for (int mt = 0; mt < 2; ++mt)
            #pragma unroll
            for (int ntl = 0; ntl < 8; ++ntl)
                #pragma unroll
                for (int c = 0; c < 4; ++c) acc[mt][ntl][c] = 0.f;

        auto stage_issue = [&](int kc, uint32_t sbase) {
            #pragma unroll
            for (int jj = 0; jj < 2; ++jj) {
                const int i = tid * 2 + jj;
                const int v = i >> 9;
                const int row = (i >> 2) & 127;
                const int q = i & 3;
                const __half* src = (v ? g_zl : g_zh) + (((size_t)ftok[row]) << 8) + kc * 32 + q * 8;
                cp16(sbase + v * A_VST + row * RSTR + q * 16, src);
            }
            #pragma unroll
            for (int jj = 0; jj < 4; ++jj) {
                const int i = tid + jj * 512;
                const int v = i >> 10;
                const int row = (i >> 2) & 255;
                const int q = i & 3;
                const __half* src = (v ? g_cl : g_ch) + (((size_t)(ct * 256 + row)) << 8) + kc * 32 + q * 8;
                cp16(sbase + RB_BASE + v * (256 * RSTR) + row * RSTR + q * 16, src);
            }
            cp_commit();
        };

        stage_issue(0, sb);
        stage_issue(1, sb + RSTAGE);

        int sidx = 0;
        for (int kc = 0; kc < 8; ++kc) {
            if (kc < 7) cp_wait<1>(); else cp_wait<0>();
            __syncthreads();
            if (kc + 2 < 8) {
                int nidx = sidx + 2; if (nidx >= 3) nidx -= 3;
                stage_issue(kc + 2, sb + nidx * RSTAGE);
            }

            const uint32_t abase = sb + sidx * RSTAGE;
            const uint32_t bbase = abase + RB_BASE;

            #pragma unroll
            for (int kg = 0; kg < 2; ++kg) {
                uint32_t ah[2][4], al[2][4];
                #pragma unroll
                for (int mt = 0; mt < 2; ++mt) {
                    const uint32_t ar = (warpM * 32 + mt * 16 + a_row) * RSTR + kg * 32 + a_coff;
                    ldm_x4(ah[mt][0], ah[mt][1], ah[mt][2], ah[mt][3], abase + ar);
                    ldm_x4(al[mt][0], al[mt][1], al[mt][2], al[mt][3], abase + A_VST + ar);
                }
                #pragma unroll
                for (int p = 0; p < 4; ++p) {
                    const uint32_t br = (warpN * 64 + p * 16 + b_row) * RSTR + kg * 32 + b_coff;
                    uint32_t b0, b1, b2, b3;
                    ldm_x4(b0, b1, b2, b3, bbase + br);
                    #pragma unroll
                    for (int mt = 0; mt < 2; ++mt) {
                        mma_f16(acc[mt][2 * p],     ah[mt], b0, b1);
                        mma_f16(acc[mt][2 * p + 1], ah[mt], b2, b3);
                    }
                    #pragma unroll
                    for (int mt = 0; mt < 2; ++mt) {
                        mma_f16(acc[mt][2 * p],     al[mt], b0, b1);
                        mma_f16(acc[mt][2 * p + 1], al[mt], b2, b3);
                    }
                    ldm_x4(b0, b1, b2, b3, bbase + 256 * RSTR + br);
                    #pragma unroll
                    for (int mt = 0; mt < 2; ++mt) {
                        mma_f16(acc[mt][2 * p],     ah[mt], b0, b1);
                        mma_f16(acc[mt][2 * p + 1], ah[mt], b2, b3);
                    }
                }
            }
            if (++sidx >= 3) sidx -= 3;
        }

        // argmin over this 256-code tile
        float v1[2][2];
        int   i1[2][2];
        #pragma unroll
        for (int mt = 0; mt < 2; ++mt)
            #pragma unroll
            for (int h = 0; h < 2; ++h) { v1[mt][h] = 3.4e38f; i1[mt][h] = 0; }
        #pragma unroll
        for (int mt = 0; mt < 2; ++mt) {
            #pragma unroll
            for (int ntl = 0; ntl < 8; ++ntl) {
                const int n0 = ct * 256 + warpN * 64 + ntl * 8 + 2 * tq;
                const float cn0 = cns[n0];
                const float cn1 = cns[n0 + 1];
                const float s00 = fmaf(-2.f, acc[mt][ntl][0], cn0);
                const float s01 = fmaf(-2.f, acc[mt][ntl][1], cn1);
                const float s10 = fmaf(-2.f, acc[mt][ntl][2], cn0);
                const float s11 = fmaf(-2.f, acc[mt][ntl][3], cn1);
                if (s00 < v1[mt][0]) { v1[mt][0] = s00; i1[mt][0] = n0; }
                if (s01 < v1[mt][0]) { v1[mt][0] = s01; i1[mt][0] = n0 + 1; }
                if (s10 < v1[mt][1]) { v1[mt][1] = s10; i1[mt][1] = n0; }
                if (s11 < v1[mt][1]) { v1[mt][1] = s11; i1[mt][1] = n0 + 1; }
            }
        }
        #pragma unroll
        for (int mt = 0; mt < 2; ++mt) {
            #pragma unroll
            for (int h = 0; h < 2; ++h) {
                float v  = v1[mt][h];
                int   ix = i1[mt][h];
                #pragma unroll
                for (int off = 1; off <= 2; off <<= 1) {
                    const float ov = __shfl_xor_sync(0xffffffffu, v, off);
                    const int   oi = __shfl_xor_sync(0xffffffffu, ix, off);
                    if (ov < v || (ov == v && oi < ix)) { v = ov; ix = oi; }
                }
                if (tq == 0) {
                    const int row = warpM * 32 + mt * 16 + h * 8 + gid;
                    sminv[warpN * 128 + row] = v;
                    smini[warpN * 128 + row] = ix;
                }
            }
        }
        __syncthreads();
        if (tid < 128) {
            float v = sminv[tid];
            int   i = smini[tid];
            #pragma unroll
            for (int wn = 1; wn < 4; ++wn) {
                const float ov = sminv[wn * 128 + tid];
                const int   oi = smini[wn * 128 + tid];
                if (ov < v || (ov == v && oi < i)) { v = ov; i = oi; }
            }
            if (tid < nt) atomicMin(&g_best[ftok[tid]], pack_si(v, i));
        }
        __syncthreads();
    }
}

// ---------------------------------------------------------------------------
// K5: apply flips + offsets scan + EMA + perplexity + loss. 1 block, 1024 thr
// ---------------------------------------------------------------------------
__global__ void k_offfin(const float* __restrict__ cb, const float* __restrict__ ema_cs,
                         float* __restrict__ out) {
    __shared__ int   sc[NUM_K];
    __shared__ float red[32];
    __shared__ float nsh, zsh;
    const int t = threadIdx.x;

    // apply recheck flips (idx, counts, Q rows)
    const int fcnt = g_flagcnt;
    for (int i = t; i < fcnt; i += 1024) {
        const int tok = g_flaglist[i];
        const int ni = (int)(g_best[tok] & 0xFFFFFFFFull);
        const int old = g_idx[tok];
        if (ni != old) {
            atomicSub(&g_counts[old], 1);
            atomicAdd(&g_counts[ni], 1);
            g_idx[tok] = ni;
            const int pos = atomicAdd(&g_flipcnt, 1);
            g_fliplist[pos] = (tok << 10) | ni;
        }
    }
    __syncthreads();
    const int nflips = g_flipcnt;
    for (int j = t; j < nflips * 256; j += 1024) {
        const int f = j >> 8, d = j & 255;
        const int packed = g_fliplist[f];
        const int tok = packed >> 10, ni = packed & 1023;
        const int b = tok >> 10, hw = tok & 1023;
        out[OFF_Q + (size_t)b * DIM * HWSZ + (size_t)d * HWSZ + hw] =
            __ldg(cb + (size_t)ni * DIM + d);
    }
    __syncthreads();

    const int c = g_counts[t];
    sc[t] = c;
    __syncthreads();
    for (int off = 1; off < NUM_K; off <<= 1) {
        const int v = (t >= off) ? sc[t - off] : 0;
        __syncthreads();
        sc[t] += v;
        __syncthreads();
    }
    const int excl = sc[t] - c;
    g_off[t] = excl;
    g_cur[t] = excl;

    float zs = g_zpart[t] + ((t < 256) ? g_minpart[t] : 0.f);
    #pragma unroll
    for (int o = 16; o > 0; o >>= 1) zs += __shfl_xor_sync(0xffffffffu, zs, o);
    if ((t & 31) == 0) red[t >> 5] = zs;
    __syncthreads();
    if (t < 32) {
        float x = red[t];
        #pragma unroll
        for (int o = 16; o > 0; o >>= 1) x += __shfl_xor_sync(0xffffffffu, x, o);
        if (t == 0) zsh = x;
    }
    __syncthreads();

    const float cnt = (float)c;
    const float ncs = ema_cs[t] * DECAYF + OMD * cnt;
    out[OFF_CS + t] = ncs;

    float s = ncs;
    #pragma unroll
    for (int o = 16; o > 0; o >>= 1) s += __shfl_xor_sync(0xffffffffu, s, o);
    if ((t & 31) == 0) red[t >> 5] = s;
    __syncthreads();
    if (t < 32) {
        float x = red[t];
        #pragma unroll
        for (int o = 16; o > 0; o >>= 1) x += __shfl_xor_sync(0xffffffffu, x, o);
        if (t == 0) nsh = x;
    }
    __syncthreads();
    const float n = nsh;
    g_csadj[t] = (ncs + EPSF) / (n + NUM_K * EPSF) * n;

    const float p = cnt / (float)NTOK;
    float s2 = p * logf(p + 1e-10f);
    #pragma unroll
    for (int o = 16; o > 0; o >>= 1) s2 += __shfl_xor_sync(0xffffffffu, s2, o);
    if ((t & 31) == 0) red[t >> 5] = s2;
    __syncthreads();
    if (t == 0) {
        float x = 0.f;
        #pragma unroll
        for (int i = 0; i < 32; i++) x += red[i];
        out[OFF_PERP] = expf(-x);
        out[OFF_LOSS] = CCOST * zsh / (float)(NTOK * DIM);
    }
}

// ---------------------------------------------------------------------------
// K6: bucket tokens by code. grid=128, block=256
// ---------------------------------------------------------------------------
__global__ void k_bucket() {
    const int tok = blockIdx.x * 256 + threadIdx.x;
    const int k = g_idx[tok];
    const int pos = atomicAdd(&g_cur[k], 1);
    g_toklist[pos] = tok;
}

// ---------------------------------------------------------------------------
// K7: dw gather (smem token list) + EMA + codebook division. grid=1024, block=256
// ---------------------------------------------------------------------------
#define MAXB 128
__global__ __launch_bounds__(256)
void k_dwfin(const float* __restrict__ ema_dw, float* __restrict__ out) {
    __shared__ int stok[MAXB];
    const int k = blockIdx.x;
    const int d = threadIdx.x;
    const int start = g_off[k];
    const int cnt   = g_counts[k];

    for (int i = d; i < cnt && i < MAXB; i += 256) stok[i] = g_toklist[start + i];
    __syncthreads();

    float acc = 0.f;
    const int csmem = (cnt < MAXB) ? cnt : MAXB;
    int i = 0;
    for (; i + 4 <= csmem; i += 4) {
        const int t0 = stok[i], t1 = stok[i + 1], t2 = stok[i + 2], t3 = stok[i + 3];
        const float v0 = __half2float(g_zh[((size_t)t0 << 8) + d]) + __half2float(g_zl[((size_t)t0 << 8) + d]);
        const float v1 = __half2float(g_zh[((size_t)t1 << 8) + d]) + __half2float(g_zl[((size_t)t1 << 8) + d]);
        const float v2 = __half2float(g_zh[((size_t)t2 << 8) + d]) + __half2float(g_zl[((size_t)t2 << 8) + d]);
        const float v3 = __half2float(g_zh[((size_t)t3 << 8) + d]) + __half2float(g_zl[((size_t)t3 << 8) + d]);
        acc += (v0 + v1) + (v2 + v3);
    }
    for (; i < csmem; ++i) {
        const size_t o = ((size_t)stok[i] << 8) + d;
        acc += __half2float(g_zh[o]) + __half2float(g_zl[o]);
    }
    for (int j = MAXB; j < cnt; ++j) {
        const size_t o = ((size_t)g_toklist[start + j] << 8) + d;
        acc += __half2float(g_zh[o]) + __half2float(g_zl[o]);
    }

    const size_t o = (size_t)k * DIM + d;
    const float nd = ema_dw[o] * DECAYF + OMD * acc;
    out[OFF_EDW + o] = nd;
    out[OFF_CB  + o] = nd / g_csadj[k];
}

// ---------------------------------------------------------------------------
extern "C" void kernel_launch(void* const* d_in, const int* in_sizes, int n_in,
                              void* d_out, int out_size) {
    const float* z      = (const float*)d_in[0];
    const float* cb     = (const float*)d_in[1];
    const float* ema_cs = (const float*)d_in[2];
    const float* ema_dw = (const float*)d_in[3];
    float* out = (float*)d_out;

    cudaFuncSetAttribute(k_argmin_mma, cudaFuncAttributeMaxDynamicSharedMemorySize, CSMEM_TOTAL);
    cudaFuncSetAttribute(k_recheck,    cudaFuncAttributeMaxDynamicSharedMemorySize, RSMEM_TOTAL);

    k_init<<<NUM_K, 64>>>(cb);
    k_zsplit<<<1024, 256>>>(z);
    k_argmin_mma<<<NTOK / 128, 512, CSMEM_TOTAL>>>(cb, out);
    k_recheck<<<112, 512, RSMEM_TOTAL>>>();           // profiled slot 4
    k_offfin<<<1, 1024>>>(cb, ema_cs, out);
    k_bucket<<<NTOK / 256, 256>>>();
    k_dwfin<<<NUM_K, 256>>>(ema_dw, out);
}